// round 11
// baseline (speedup 1.0000x reference)
#include <cuda_runtime.h>
#include <cuda_fp16.h>
#include <cstdint>

// ---------------- problem constants ----------------
#define MM      16
#define NN      8192
#define KK      8192
#define GS      128
#define KSPLIT  8
#define KRANGE  (KK / KSPLIT)        // 1024 k per CTA
#define KBLKS   (KRANGE / 16)        // 64 k16-blocks
#define NGRP    (KRANGE / GS)        // 8 scale groups per CTA
#define TPB     128                  // 4 warps
#define WCOLS   16                   // columns per warp (2 n-tiles of 8)
#define CTACOLS 64
#define NCTA_N  (NN / CTACOLS)       // 128 -> grid = 128 x 8 = 1024 CTAs
#define XS_STRIDE 1032               // halves; 516 words/row -> bank (4g+c)%32 distinct

// 8 * 16 * 8192 f32 = 4 MiB K-split partials
__device__ float g_part[(size_t)KSPLIT * MM * NN];

// raw dequant: ((w >> 4c) & 0x000F000F) | 0x64006400 = fp16x2 (1024+q[c], 1024+q[c+4])
// offset (-1032) and scale are deferred to the f32 group-boundary fixup.
static __device__ __forceinline__ uint32_t dqraw(uint32_t w, uint32_t sh4) {
    uint32_t v;
    const uint32_t t = w >> sh4;
    asm("lop3.b32 %0, %1, 0x000F000F, 0x64006400, 0xEA;" : "=r"(v) : "r"(t));
    return v;
}

static __device__ __forceinline__ void hmma16816(float* d, uint32_t a0, uint32_t a1,
                                                 uint32_t a2, uint32_t a3,
                                                 uint32_t b0, uint32_t b1) {
    asm volatile(
        "mma.sync.aligned.m16n8k16.row.col.f32.f16.f16.f32 "
        "{%0,%1,%2,%3}, {%4,%5,%6,%7}, {%8,%9}, {%0,%1,%2,%3};"
        : "+f"(d[0]), "+f"(d[1]), "+f"(d[2]), "+f"(d[3])
        : "r"(a0), "r"(a1), "r"(a2), "r"(a3), "r"(b0), "r"(b1));
}

// ---------------- stage 1: raw-HMMA + f32 group fixup ----------------
__global__ void __launch_bounds__(TPB, 6)
fp4hmma_stage1(const float* __restrict__ x,       // [16, 8192] f32 (exact fp16 values)
               const int*   __restrict__ wp,      // [1024, 8192] int32 packed FP4
               const float* __restrict__ scales)  // [64, 8192] f32 (exact fp16 values)
{
    __shared__ __align__(16) __half xs[MM][XS_STRIDE];
    __shared__ float rsum[MM][NGRP];   // 1032 * sum_{k in group} x[m][k]

    const int tid  = threadIdx.x;
    const int wrp  = tid >> 5;        // 0..3
    const int lane = tid & 31;
    const int g    = lane >> 2;       // 0..7
    const int c    = lane & 3;        // 0..3
    const int kb0  = blockIdx.y * KRANGE;

    // ---- stage x slice [16 x 1024] as fp16, k-permuted per 8-k sub-block:
    // position 2j holds k=j, position 2j+1 holds k=j+4  (j = 0..3)
    #pragma unroll
    for (int it = 0; it < 16; ++it) {
        const int p  = tid + it * TPB;        // 8-float chunk id 0..2047
        const int m  = p >> 7;                // 128 chunks per row
        const int k8 = (p & 127) << 3;
        const float4 va = *(const float4*)&x[(size_t)m * KK + kb0 + k8];
        const float4 vb = *(const float4*)&x[(size_t)m * KK + kb0 + k8 + 4];
        *(__half2*)&xs[m][k8]     = __floats2half2_rn(va.x, vb.x);
        *(__half2*)&xs[m][k8 + 2] = __floats2half2_rn(va.y, vb.y);
        *(__half2*)&xs[m][k8 + 4] = __floats2half2_rn(va.z, vb.z);
        *(__half2*)&xs[m][k8 + 6] = __floats2half2_rn(va.w, vb.w);
    }
    __syncthreads();

    // ---- per-(m, group) row sums, deterministic sequential order ----
    {
        const int m  = tid >> 3;              // 16 rows
        const int gr = tid & 7;               // 8 groups
        const __half2* p = (const __half2*)&xs[m][gr * GS];
        float s = 0.0f;
        #pragma unroll
        for (int i = 0; i < GS / 2; ++i) {
            const float2 f = __half22float2(p[i]);
            s += f.x;
            s += f.y;
        }
        rsum[m][gr] = 1032.0f * s;
    }
    __syncthreads();

    const int wb = blockIdx.x * CTACOLS + wrp * WCOLS;

    float acc_s[2][4];   // scaled output accumulators
    float acc_g[2][4];   // raw per-group accumulators
    #pragma unroll
    for (int t = 0; t < 2; ++t)
        #pragma unroll
        for (int r = 0; r < 4; ++r) { acc_s[t][r] = 0.0f; acc_g[t][r] = 0.0f; }

    const uint32_t sh4   = (uint32_t)c * 4u;
    const int      prow0 = blockIdx.y * (KRANGE / 8);
    const int*     wbase = &wp[(size_t)prow0 * NN + wb + g];

    // two 16-word buffers; each holds 4 k-blocks:
    // buf[j*4 + row*2 + t], j = sub-kb 0..3, row = packed row 0/1, t = n-tile 0/1
    uint32_t bufA[16], bufB[16];

    #define PREFETCH(buf, kbb)                                                  \
        {                                                                       \
            _Pragma("unroll")                                                   \
            for (int j = 0; j < 4; ++j) {                                       \
                const int* p = wbase + (size_t)((kbb) + j) * 2 * NN;            \
                (buf)[j * 4 + 0] = (uint32_t)p[0];                              \
                (buf)[j * 4 + 1] = (uint32_t)p[8];                              \
                (buf)[j * 4 + 2] = (uint32_t)p[NN];                             \
                (buf)[j * 4 + 3] = (uint32_t)p[NN + 8];                         \
            }                                                                   \
        }

    #define CONSUME(buf, kbb)                                                   \
        {                                                                       \
            _Pragma("unroll")                                                   \
            for (int j = 0; j < 4; ++j) {                                       \
                const int klo = ((kbb) + j) * 16 + c * 2;                       \
                const uint32_t a0 = *(const uint32_t*)&xs[g][klo];              \
                const uint32_t a1 = *(const uint32_t*)&xs[g + 8][klo];          \
                const uint32_t a2 = *(const uint32_t*)&xs[g][klo + 8];          \
                const uint32_t a3 = *(const uint32_t*)&xs[g + 8][klo + 8];      \
                hmma16816(acc_g[0], a0, a1, a2, a3,                             \
                          dqraw((buf)[j * 4 + 0], sh4),                         \
                          dqraw((buf)[j * 4 + 2], sh4));                        \
                hmma16816(acc_g[1], a0, a1, a2, a3,                             \
                          dqraw((buf)[j * 4 + 1], sh4),                         \
                          dqraw((buf)[j * 4 + 3], sh4));                        \
            }                                                                   \
        }

    #define FIXUP(gr)                                                           \
        {                                                                       \
            const float Ca = rsum[g][(gr)];                                     \
            const float Cb = rsum[g + 8][(gr)];                                 \
            const size_t srow = (size_t)(blockIdx.y * NGRP + (gr)) * NN;        \
            _Pragma("unroll")                                                   \
            for (int t = 0; t < 2; ++t) {                                       \
                const int n0 = wb + t * 8 + 2 * c;                              \
                const float s0 = 0.5f * scales[srow + n0];                      \
                const float s1 = 0.5f * scales[srow + n0 + 1];                  \
                acc_s[t][0] += s0 * (acc_g[t][0] - Ca);                         \
                acc_s[t][1] += s1 * (acc_g[t][1] - Ca);                         \
                acc_s[t][2] += s0 * (acc_g[t][2] - Cb);                         \
                acc_s[t][3] += s1 * (acc_g[t][3] - Cb);                         \
                acc_g[t][0] = 0.0f; acc_g[t][1] = 0.0f;                         \
                acc_g[t][2] = 0.0f; acc_g[t][3] = 0.0f;                         \
            }                                                                   \
        }

    PREFETCH(bufA, 0)
    PREFETCH(bufB, 4)

    // macro-iteration = 8 k-blocks = exactly one scale group
    #pragma unroll 1
    for (int kb = 0; kb < KBLKS; kb += 8) {
        if (kb > 0) FIXUP((kb >> 3) - 1)

        CONSUME(bufA, kb)
        {
            const int kbn = (kb + 8 < KBLKS) ? kb + 8 : kb;
            PREFETCH(bufA, kbn)
        }
        CONSUME(bufB, kb + 4)
        {
            const int kbn = (kb + 12 < KBLKS) ? kb + 12 : kb;
            PREFETCH(bufB, kbn)
        }
    }
    FIXUP(NGRP - 1)

    // ---- epilogue: write K-split partials ----
    const size_t pbase = (size_t)blockIdx.y * MM * NN;
    #pragma unroll
    for (int t = 0; t < 2; ++t) {
        const int n = wb + t * 8 + c * 2;
        *(float2*)&g_part[pbase + (size_t)g * NN + n]       = make_float2(acc_s[t][0], acc_s[t][1]);
        *(float2*)&g_part[pbase + (size_t)(g + 8) * NN + n] = make_float2(acc_s[t][2], acc_s[t][3]);
    }

    #undef PREFETCH
    #undef CONSUME
    #undef FIXUP
}

// ---------------- stage 2: float2 loads, register tree sum ----------------
__global__ void __launch_bounds__(256)
fp4hmma_reduce(float* __restrict__ out)
{
    const int i2 = (blockIdx.x * 256 + threadIdx.x) * 2;   // 2 consecutive outputs
    float2 v[KSPLIT];
    #pragma unroll
    for (int i = 0; i < KSPLIT; ++i)
        v[i] = *(const float2*)&g_part[(size_t)i * MM * NN + i2];
    #pragma unroll
    for (int stride = 1; stride < KSPLIT; stride <<= 1)
        #pragma unroll
        for (int i = 0; i < KSPLIT; i += 2 * stride) {
            v[i].x += v[i + stride].x;
            v[i].y += v[i + stride].y;
        }
    float2 r;
    r.x = __half2float(__float2half(v[0].x));
    r.y = __half2float(__float2half(v[0].y));
    *(float2*)&out[i2] = r;
}

extern "C" void kernel_launch(void* const* d_in, const int* in_sizes, int n_in,
                              void* d_out, int out_size)
{
    const float* x      = (const float*)d_in[0];
    const int*   wp     = (const int*)  d_in[1];
    const float* scales = (const float*)d_in[2];
    float*       out    = (float*)d_out;

    dim3 grid(NCTA_N, KSPLIT);
    fp4hmma_stage1<<<grid, TPB>>>(x, wp, scales);
    fp4hmma_reduce<<<(MM * NN) / (256 * 2), 256>>>(out);
}

// round 12
// speedup vs baseline: 1.4333x; 1.4333x over previous
#include <cuda_runtime.h>
#include <cuda_fp16.h>
#include <cstdint>

// ---------------- problem constants ----------------
#define MM      16
#define NN      8192
#define KK      8192
#define GS      128
#define KSPLIT  16
#define KRANGE  (KK / KSPLIT)        // 512 k per CTA
#define KBLKS   (KRANGE / 16)        // 32 k16-blocks
#define NGRP    (KRANGE / GS)        // 4 scale groups per CTA
#define TPB     128                  // 4 warps
#define WCOLS   32                   // columns per warp (4 n-tiles of 8)
#define CTACOLS 128
#define NCTA_N  (NN / CTACOLS)       // 64  -> grid = 64 x 16 = 1024 CTAs
#define XS_STRIDE 520                // halves; word-bank (4g+c)%32 distinct

// 16 * 16 * 8192 f32 = 8 MiB K-split partials
__device__ float g_part[(size_t)KSPLIT * MM * NN];

// k-permuted dequant: ((w >> 4c) & 0x000F000F) | 0x64006400 gives fp16x2
// (1024+q[c], 1024+q[c+4]) in ONE LOP3 after the shift.  Slots (2c,2c+1)
// carry k=(c,c+4); x is staged into SMEM with the matching permutation.
static __device__ __forceinline__ __half2 dq4(uint32_t w, uint32_t sh4, __half2 s2) {
    uint32_t v;
    const uint32_t t = w >> sh4;
    asm("lop3.b32 %0, %1, 0x000F000F, 0x64006400, 0xEA;" : "=r"(v) : "r"(t));
    const uint32_t m1032 = 0xE408E408u;   // fp16x2 (-1032, -1032)
    __half2 h = __hadd2(*reinterpret_cast<__half2*>(&v),
                        *reinterpret_cast<const __half2*>(&m1032)); // (q-8) exact
    return __hmul2(h, s2);
}

static __device__ __forceinline__ void hmma16816(float* d, uint32_t a0, uint32_t a1,
                                                 uint32_t a2, uint32_t a3,
                                                 uint32_t b0, uint32_t b1) {
    asm volatile(
        "mma.sync.aligned.m16n8k16.row.col.f32.f16.f16.f32 "
        "{%0,%1,%2,%3}, {%4,%5,%6,%7}, {%8,%9}, {%0,%1,%2,%3};"
        : "+f"(d[0]), "+f"(d[1]), "+f"(d[2]), "+f"(d[3])
        : "r"(a0), "r"(a1), "r"(a2), "r"(a3), "r"(b0), "r"(b1));
}

// ---------------- stage 1: dequant-to-register + HMMA (R9 configuration) ----------------
__global__ void __launch_bounds__(TPB, 6)
fp4hmma_stage1(const float* __restrict__ x,       // [16, 8192] f32 (exact fp16 values)
               const int*   __restrict__ wp,      // [1024, 8192] int32 packed FP4
               const float* __restrict__ scales)  // [64, 8192] f32 (exact fp16 values)
{
    __shared__ __align__(16) __half xs[MM][XS_STRIDE];

    const int tid  = threadIdx.x;
    const int wrp  = tid >> 5;        // 0..3
    const int lane = tid & 31;
    const int g    = lane >> 2;       // 0..7
    const int c    = lane & 3;        // 0..3
    const int kb0  = blockIdx.y * KRANGE;

    // ---- stage x slice [16 x 512] as fp16, k-PERMUTED per 8-k sub-block:
    // position 2j holds k=j, position 2j+1 holds k=j+4  (j = 0..3)
    #pragma unroll
    for (int it = 0; it < 8; ++it) {
        const int p  = tid + it * TPB;        // 8-float chunk id 0..1023
        const int m  = p >> 6;                // 64 chunks per row
        const int k8 = (p & 63) << 3;
        const float4 va = *(const float4*)&x[(size_t)m * KK + kb0 + k8];
        const float4 vb = *(const float4*)&x[(size_t)m * KK + kb0 + k8 + 4];
        *(__half2*)&xs[m][k8]     = __floats2half2_rn(va.x, vb.x);
        *(__half2*)&xs[m][k8 + 2] = __floats2half2_rn(va.y, vb.y);
        *(__half2*)&xs[m][k8 + 4] = __floats2half2_rn(va.z, vb.z);
        *(__half2*)&xs[m][k8 + 6] = __floats2half2_rn(va.w, vb.w);
    }
    __syncthreads();

    const int wb = blockIdx.x * CTACOLS + wrp * WCOLS;

    float acc[4][4];
    #pragma unroll
    for (int t = 0; t < 4; ++t)
        #pragma unroll
        for (int r = 0; r < 4; ++r) acc[t][r] = 0.0f;

    const uint32_t sh4   = (uint32_t)c * 4u;
    const int      prow0 = blockIdx.y * (KRANGE / 8);

    float snext[4];
    #pragma unroll
    for (int t = 0; t < 4; ++t)
        snext[t] = scales[(size_t)(blockIdx.y * NGRP) * NN + wb + t * 8 + g];
    __half2 s2[4];

    // weight double-buffer: wA/wB hold 8 words ({row0 t0..3, row1 t0..3})
    const int* wbase = &wp[(size_t)prow0 * NN + wb + g];
    uint32_t wA[8], wB[8];
    #pragma unroll
    for (int t = 0; t < 4; ++t) {
        wA[t]     = (uint32_t)wbase[t * 8];
        wA[4 + t] = (uint32_t)wbase[(size_t)NN + t * 8];
    }

    #pragma unroll 1
    for (int kb = 0; kb < KBLKS; kb += 2) {
        if ((kb & 7) == 0) {
            #pragma unroll
            for (int t = 0; t < 4; ++t)
                s2[t] = __half2half2(__float2half_rn(0.5f * snext[t]));
            const int gn = ((kb >> 3) + 1 < NGRP) ? (kb >> 3) + 1 : (kb >> 3);
            const size_t grow = (size_t)(blockIdx.y * NGRP + gn) * NN;
            #pragma unroll
            for (int t = 0; t < 4; ++t)
                snext[t] = scales[grow + wb + t * 8 + g];
        }

        // prefetch k-block kb+1 into wB
        {
            const int* p = wbase + (size_t)(kb + 1) * 2 * NN;
            #pragma unroll
            for (int t = 0; t < 4; ++t) {
                wB[t]     = (uint32_t)p[t * 8];
                wB[4 + t] = (uint32_t)p[(size_t)NN + t * 8];
            }
        }

        // consume wA (k-block kb)
        {
            const int klo = kb * 16 + c * 2;
            const uint32_t a0 = *(const uint32_t*)&xs[g][klo];
            const uint32_t a1 = *(const uint32_t*)&xs[g + 8][klo];
            const uint32_t a2 = *(const uint32_t*)&xs[g][klo + 8];
            const uint32_t a3 = *(const uint32_t*)&xs[g + 8][klo + 8];
            #pragma unroll
            for (int t = 0; t < 4; ++t) {
                const __half2 b0 = dq4(wA[t], sh4, s2[t]);
                const __half2 b1 = dq4(wA[4 + t], sh4, s2[t]);
                hmma16816(acc[t], a0, a1, a2, a3,
                          *(const uint32_t*)&b0, *(const uint32_t*)&b1);
            }
        }

        // prefetch k-block kb+2 into wA (clamped)
        {
            const int kbn = (kb + 2 < KBLKS) ? kb + 2 : kb;
            const int* p = wbase + (size_t)kbn * 2 * NN;
            #pragma unroll
            for (int t = 0; t < 4; ++t) {
                wA[t]     = (uint32_t)p[t * 8];
                wA[4 + t] = (uint32_t)p[(size_t)NN + t * 8];
            }
        }

        // consume wB (k-block kb+1)
        {
            const int klo = (kb + 1) * 16 + c * 2;
            const uint32_t a0 = *(const uint32_t*)&xs[g][klo];
            const uint32_t a1 = *(const uint32_t*)&xs[g + 8][klo];
            const uint32_t a2 = *(const uint32_t*)&xs[g][klo + 8];
            const uint32_t a3 = *(const uint32_t*)&xs[g + 8][klo + 8];
            #pragma unroll
            for (int t = 0; t < 4; ++t) {
                const __half2 b0 = dq4(wB[t], sh4, s2[t]);
                const __half2 b1 = dq4(wB[4 + t], sh4, s2[t]);
                hmma16816(acc[t], a0, a1, a2, a3,
                          *(const uint32_t*)&b0, *(const uint32_t*)&b1);
            }
        }
    }

    // ---- epilogue: write K-split partials ----
    const size_t pbase = (size_t)blockIdx.y * MM * NN;
    #pragma unroll
    for (int t = 0; t < 4; ++t) {
        const int n = wb + t * 8 + c * 2;
        *(float2*)&g_part[pbase + (size_t)g * NN + n]       = make_float2(acc[t][0], acc[t][1]);
        *(float2*)&g_part[pbase + (size_t)(g + 8) * NN + n] = make_float2(acc[t][2], acc[t][3]);
    }
}

// ---------------- stage 2: one output per thread, 1024 CTAs for overlap ----------------
__global__ void __launch_bounds__(128)
fp4hmma_reduce(float* __restrict__ out)
{
    const int idx = blockIdx.x * 128 + threadIdx.x;   // m*NN + n, 131072 threads
    float v[KSPLIT];
    #pragma unroll
    for (int i = 0; i < KSPLIT; ++i)
        v[i] = g_part[(size_t)i * MM * NN + idx];     // 16 coalesced loads in flight
    #pragma unroll
    for (int stride = 1; stride < KSPLIT; stride <<= 1)
        #pragma unroll
        for (int i = 0; i < KSPLIT; i += 2 * stride)
            v[i] += v[i + stride];
    out[idx] = __half2float(__float2half(v[0]));
}

extern "C" void kernel_launch(void* const* d_in, const int* in_sizes, int n_in,
                              void* d_out, int out_size)
{
    const float* x      = (const float*)d_in[0];
    const int*   wp     = (const int*)  d_in[1];
    const float* scales = (const float*)d_in[2];
    float*       out    = (float*)d_out;

    dim3 grid(NCTA_N, KSPLIT);
    fp4hmma_stage1<<<grid, TPB>>>(x, wp, scales);
    fp4hmma_reduce<<<(MM * NN) / 128, 128>>>(out);
}